// round 13
// baseline (speedup 1.0000x reference)
#include <cuda_runtime.h>
#include <cuda_bf16.h>
#include <math.h>
#include <stdint.h>

#define B_  2
#define S_  1024
#define D_  1024
#define NH_ 8
#define QKS_ 1024
#define Vd_ 1024
#define DQK_ 64
#define DHV_ 128
#define CAP_ 15.0f
#define NORM_EPS_ 1e-6f
#define DENOM_EPS_ 1e-6f
#define L_   64
#define NC_  (S_/L_)
#define NEGINF_ (-1e30f)

// ================= ptx helpers =================
__device__ __forceinline__ uint32_t smem_u32(const void* p) {
    uint32_t a;
    asm("{ .reg .u64 t; cvta.to.shared.u64 t, %1; cvt.u32.u64 %0, t; }" : "=r"(a) : "l"(p));
    return a;
}
#define CP_ASYNC16(dst, src) \
    asm volatile("cp.async.cg.shared.global [%0], [%1], 16;" :: "r"(dst), "l"(src))
#define CP_COMMIT() asm volatile("cp.async.commit_group;" ::: "memory")
#define CP_WAIT0()  asm volatile("cp.async.wait_group 0;" ::: "memory")
#define CP_WAIT1()  asm volatile("cp.async.wait_group 1;" ::: "memory")

#define LDMATRIX_X4(r0, r1, r2, r3, addr) \
    asm volatile("ldmatrix.sync.aligned.m8n8.x4.shared.b16 {%0,%1,%2,%3}, [%4];" \
        : "=r"(r0), "=r"(r1), "=r"(r2), "=r"(r3) : "r"(addr))

#define MMA16816(c, a, b0, b1) \
    asm volatile("mma.sync.aligned.m16n8k16.row.col.f32.bf16.bf16.f32 " \
        "{%0,%1,%2,%3}, {%4,%5,%6,%7}, {%8,%9}, {%0,%1,%2,%3};" \
        : "+f"((c)[0]), "+f"((c)[1]), "+f"((c)[2]), "+f"((c)[3]) \
        : "r"((a)[0]), "r"((a)[1]), "r"((a)[2]), "r"((a)[3]), "r"(b0), "r"(b1))

// ---------------- device scratch ----------------
__device__ float  g_qk  [B_*S_*QKS_];
__device__ float  g_v   [B_*S_*Vd_];
__device__ float  g_opre[B_*S_*Vd_];
__device__ float  g_ipre[B_*S_*NH_];
__device__ float  g_fpre[B_*S_*NH_];
__device__ float2 g_bm  [B_*NH_*S_];
__device__ float  g_state [B_*NH_*NC_*DQK_*DHV_];
__device__ float  g_nstate[B_*NH_*NC_*DQK_];

__device__ __align__(16) __nv_bfloat16 g_xhi[B_*S_*D_],  g_xlo[B_*S_*D_];
__device__ __align__(16) __nv_bfloat16 g_wqkhi[QKS_*D_], g_wqklo[QKS_*D_];
__device__ __align__(16) __nv_bfloat16 g_wvhi[Vd_*D_],   g_wvlo[Vd_*D_];
__device__ __align__(16) __nv_bfloat16 g_woghi[Vd_*D_],  g_woglo[Vd_*D_];
__device__ __align__(16) __nv_bfloat16 g_wouthi[D_*Vd_], g_woutlo[D_*Vd_];
__device__ __align__(16) __nv_bfloat16 g_hhi[B_*S_*Vd_], g_hlo[B_*S_*Vd_];

// ---------------- fused (cvt hi/lo split) + (gate projections) -------------
struct CvtArgs {
    const float4* src[6];
    uint2* hi[6];
    uint2* lo[6];
    int    end[6];
};

__device__ __forceinline__ float softcap15(float x) {
    return CAP_ * tanhf(x * (1.0f / CAP_));
}

__global__ __launch_bounds__(256)
void cvt_gates(CvtArgs a, const float* __restrict__ x,
               const float* __restrict__ Wi, const float* __restrict__ bi,
               const float* __restrict__ Wf, const float* __restrict__ bf,
               int cvtBlocks)
{
    if ((int)blockIdx.x < cvtBlocks) {
        int gi = blockIdx.x * 256 + threadIdx.x;
        if (gi >= a.end[5]) return;
        int seg = 0, base = 0;
#pragma unroll
        for (int s = 0; s < 5; s++)
            if (gi >= a.end[s]) { seg = s + 1; base = a.end[s]; }
        int i = gi - base;

        float4 v = a.src[seg][i];
        __nv_bfloat16 h0 = __float2bfloat16(v.x), h1 = __float2bfloat16(v.y);
        __nv_bfloat16 h2 = __float2bfloat16(v.z), h3 = __float2bfloat16(v.w);
        __nv_bfloat16 l0 = __float2bfloat16(v.x - __bfloat162float(h0));
        __nv_bfloat16 l1 = __float2bfloat16(v.y - __bfloat162float(h1));
        __nv_bfloat16 l2 = __float2bfloat16(v.z - __bfloat162float(h2));
        __nv_bfloat16 l3 = __float2bfloat16(v.w - __bfloat162float(h3));
        uint2 hv, lv;
        hv.x = (uint32_t)__bfloat16_as_ushort(h0) | ((uint32_t)__bfloat16_as_ushort(h1) << 16);
        hv.y = (uint32_t)__bfloat16_as_ushort(h2) | ((uint32_t)__bfloat16_as_ushort(h3) << 16);
        lv.x = (uint32_t)__bfloat16_as_ushort(l0) | ((uint32_t)__bfloat16_as_ushort(l1) << 16);
        lv.y = (uint32_t)__bfloat16_as_ushort(l2) | ((uint32_t)__bfloat16_as_ushort(l3) << 16);
        a.hi[seg][i] = hv;
        a.lo[seg][i] = lv;
    } else {
        int row  = ((blockIdx.x - cvtBlocks) * 256 + threadIdx.x) >> 5;
        int lane = threadIdx.x & 31;
        if (row >= B_ * S_) return;

        const float4* xr = (const float4*)(x + (size_t)row * D_);
        float4 xv[8];
#pragma unroll
        for (int k = 0; k < 8; k++) xv[k] = xr[lane + 32*k];

#pragma unroll
        for (int h = 0; h < NH_; h++) {
            const float4* wi = (const float4*)(Wi + (size_t)h * D_);
            const float4* wf = (const float4*)(Wf + (size_t)h * D_);
            float ai = 0.f, af = 0.f;
#pragma unroll
            for (int k = 0; k < 8; k++) {
                float4 iv = wi[lane + 32*k];
                float4 fv = wf[lane + 32*k];
                ai = fmaf(xv[k].x, iv.x, ai); ai = fmaf(xv[k].y, iv.y, ai);
                ai = fmaf(xv[k].z, iv.z, ai); ai = fmaf(xv[k].w, iv.w, ai);
                af = fmaf(xv[k].x, fv.x, af); af = fmaf(xv[k].y, fv.y, af);
                af = fmaf(xv[k].z, fv.z, af); af = fmaf(xv[k].w, fv.w, af);
            }
#pragma unroll
            for (int off = 16; off; off >>= 1) {
                ai += __shfl_xor_sync(0xffffffffu, ai, off);
                af += __shfl_xor_sync(0xffffffffu, af, off);
            }
            if (lane == 0) {
                g_ipre[row*NH_ + h] = softcap15(ai + bi[h]);
                g_fpre[row*NH_ + h] = softcap15(af + bf[h]);
            }
        }
    }
}

// ---------------- warp-MMA bf16x3-split GEMM body --------------------------
#define GSTAGE 40960
#define GMAT   10240

__device__ __forceinline__
void gemm_body(const __nv_bfloat16* __restrict__ Ahi, const __nv_bfloat16* __restrict__ Alo,
               const __nv_bfloat16* __restrict__ Bhi, const __nv_bfloat16* __restrict__ Blo,
               float* __restrict__ C, int K, int ldc,
               unsigned char* smem, int bx, int by)
{
    const uint32_t smem_base = smem_u32(smem);

    const int tid = threadIdx.x;
    const int wid = tid >> 5;
    const int lane = tid & 31;
    const int warp_m = wid & 3;
    const int warp_n = wid >> 2;
    const int blockRow = by * 128;
    const int blockCol = bx * 128;

    const __nv_bfloat16* bases[4] = {
        Ahi + (size_t)blockRow * K, Alo + (size_t)blockRow * K,
        Bhi + (size_t)blockCol * K, Blo + (size_t)blockCol * K };

    float acc[2][8][4];
#pragma unroll
    for (int i = 0; i < 2; i++)
#pragma unroll
        for (int j = 0; j < 8; j++)
#pragma unroll
            for (int q = 0; q < 4; q++) acc[i][j][q] = 0.f;

    const int nch = K >> 5;

#define LOAD_STAGE(buf, stage) do {                                            \
        const int kc0 = (stage) << 5;                                          \
        _Pragma("unroll")                                                      \
        for (int i = 0; i < 8; i++) {                                          \
            const int m  = i >> 1;                                             \
            const int cm = ((i & 1) << 8) + tid;                               \
            const int row = cm >> 2;                                           \
            const int cc  = cm & 3;                                            \
            const __nv_bfloat16* src = bases[m] + (size_t)row * K + kc0 + cc * 8; \
            uint32_t dst = smem_base + (buf) * GSTAGE + m * GMAT + row * 80 + cc * 16; \
            CP_ASYNC16(dst, src);                                              \
        }                                                                      \
        CP_COMMIT();                                                           \
    } while (0)

    LOAD_STAGE(0, 0);

    for (int c = 0; c < nch; c++) {
        const int buf = c & 1;
        if (c + 1 < nch) {
            LOAD_STAGE((c + 1) & 1, c + 1);
            CP_WAIT1();
        } else {
            CP_WAIT0();
        }
        __syncthreads();

        const uint32_t sa = smem_base + buf * GSTAGE + (warp_m * 32) * 80;
        const uint32_t sb = smem_base + buf * GSTAGE + 2 * GMAT + (warp_n * 64) * 80;
        const int a_row = lane & 15;
        const int a_kb  = (lane >> 4) << 4;
        const int b_row = (lane & 7) + ((lane >> 4) << 3);
        const int b_kb  = ((lane >> 3) & 1) << 4;

#pragma unroll
        for (int kk = 0; kk < 2; kk++) {
            uint32_t ah[2][4], al[2][4];
#pragma unroll
            for (int mt = 0; mt < 2; mt++) {
                uint32_t addr = sa + (mt * 16 + a_row) * 80 + kk * 32 + a_kb;
                LDMATRIX_X4(ah[mt][0], ah[mt][1], ah[mt][2], ah[mt][3], addr);
                addr += GMAT;
                LDMATRIX_X4(al[mt][0], al[mt][1], al[mt][2], al[mt][3], addr);
            }
#pragma unroll
            for (int gp = 0; gp < 2; gp++) {
                uint32_t bh[2][4], bl[2][4];
#pragma unroll
                for (int g2 = 0; g2 < 2; g2++) {
                    uint32_t addr = sb + ((gp * 2 + g2) * 16 + b_row) * 80 + kk * 32 + b_kb;
                    LDMATRIX_X4(bh[g2][0], bh[g2][1], bh[g2][2], bh[g2][3], addr);
                    addr += GMAT;
                    LDMATRIX_X4(bl[g2][0], bl[g2][1], bl[g2][2], bl[g2][3], addr);
                }
#pragma unroll
                for (int term = 0; term < 3; term++) {
#pragma unroll
                    for (int g2 = 0; g2 < 2; g2++)
#pragma unroll
                        for (int half = 0; half < 2; half++)
#pragma unroll
                            for (int mt = 0; mt < 2; mt++) {
                                const int nt = (gp * 2 + g2) * 2 + half;
                                const uint32_t* aa = (term == 2) ? al[mt] : ah[mt];
                                const uint32_t* bb = (term == 1) ? bl[g2] : bh[g2];
                                MMA16816(acc[mt][nt], aa, bb[half * 2], bb[half * 2 + 1]);
                            }
                }
            }
        }
        __syncthreads();
    }

    const int r0 = blockRow + warp_m * 32 + (lane >> 2);
    const int c0 = blockCol + warp_n * 64 + (lane & 3) * 2;
#pragma unroll
    for (int mt = 0; mt < 2; mt++) {
#pragma unroll
        for (int nt = 0; nt < 8; nt++) {
            float* p0 = C + (size_t)(r0 + mt * 16)     * ldc + c0 + nt * 8;
            float* p1 = C + (size_t)(r0 + mt * 16 + 8) * ldc + c0 + nt * 8;
            *(float2*)p0 = make_float2(acc[mt][nt][0], acc[mt][nt][1]);
            *(float2*)p1 = make_float2(acc[mt][nt][2], acc[mt][nt][3]);
        }
    }
#undef LOAD_STAGE
}

// ---------------- gate scan body: 256 threads, 4 timesteps/thread ----------
__device__ void scan_body(float* sm, int bh)
{
    float* wF = sm;
    float* wI = sm + 8;

    int b = bh >> 3, h = bh & 7;
    int tid = threadIdx.x, lane = tid & 31, warp = tid >> 5;
    int t0 = tid * 4;

    float Fe[4], Ie[4];
    float Fl = 0.f, Il = NEGINF_;
#pragma unroll
    for (int j = 0; j < 4; j++) {
        int t = t0 + j;
        float fp = g_fpre[(size_t)(b*S_+t)*NH_ + h];
        float ip = g_ipre[(size_t)(b*S_+t)*NH_ + h];
        float F = (fp >= 0.f) ? -log1pf(expf(-fp)) : (fp - log1pf(expf(fp)));
        Fe[j] = F; Ie[j] = ip;
        Il = fmaxf(Il + F, ip);
        Fl = Fl + F;
    }

    float Fi = Fl, Ii = Il;
#pragma unroll
    for (int off = 1; off < 32; off <<= 1) {
        float Fp = __shfl_up_sync(0xffffffffu, Fi, off);
        float Ip = __shfl_up_sync(0xffffffffu, Ii, off);
        if (lane >= off) {
            Ii = fmaxf(Ip + Fi, Ii);
            Fi = Fp + Fi;
        }
    }
    if (lane == 31) { wF[warp] = Fi; wI[warp] = Ii; }
    __syncthreads();

    if (warp == 0 && lane < 8) {
        float Fw = wF[lane], Iw = wI[lane];
#pragma unroll
        for (int off = 1; off < 8; off <<= 1) {
            float Fp = __shfl_up_sync(0x000000ffu, Fw, off);
            float Ip = __shfl_up_sync(0x000000ffu, Iw, off);
            if (lane >= off) {
                Iw = fmaxf(Ip + Fw, Iw);
                Fw = Fp + Fw;
            }
        }
        wF[lane] = Fw; wI[lane] = Iw;
    }
    __syncthreads();

    float Fprev = __shfl_up_sync(0xffffffffu, Fi, 1);
    float Iprev = __shfl_up_sync(0xffffffffu, Ii, 1);
    if (lane == 0) { Fprev = 0.f; Iprev = NEGINF_; }
    if (warp > 0) {
        float Fw = wF[warp - 1], Iw = wI[warp - 1];
        Iprev = fmaxf(Iw + Fprev, Iprev);
        Fprev = Fw + Fprev;
    }

    float Fc = Fprev, Ic = Iprev;
#pragma unroll
    for (int j = 0; j < 4; j++) {
        Ic = fmaxf(Ic + Fe[j], Ie[j]);
        Fc = Fc + Fe[j];
        g_bm[(size_t)bh*S_ + t0 + j] = make_float2(Fc, fmaxf(Fc, Ic));
    }
}

// ---------------- state pass body (uses dynamic smem) -----------------------
__device__ void state_body(float* sm, int vq, int bh)
{
    float* Ks   = sm;
    float* Vs   = Ks + 64*68;
    float* uarr = Vs + 64*36;
    float* narr = uarr + 64;
    float* lamp = narr + 64;

    int b = bh >> 3, h = bh & 7;
    int tid = threadIdx.x;
    int ty = tid >> 5;
    int tx = tid & 31;

    float acc[8];
#pragma unroll
    for (int j = 0; j < 8; j++) acc[j] = 0.f;
    if (tid < DQK_) narr[tid] = 0.f;

    float Bc = 0.f, Mc = 0.f;
    __syncthreads();

    for (int c = 0; c < NC_; c++) {
        float* st = g_state + ((size_t)(bh*NC_ + c)) * (DQK_*DHV_);
#pragma unroll
        for (int j = 0; j < 8; j++)
            st[(ty*8 + j)*DHV_ + vq*32 + tx] = acc[j];
        if (vq == 0 && tid < DQK_)
            g_nstate[(size_t)(bh*NC_ + c)*DQK_ + tid] = narr[tid];

        float2 bmn = g_bm[(size_t)bh*S_ + c*L_ + (L_-1)];
        float Bn = bmn.x, Mn = bmn.y;

        if (tid < L_) {
            int t = c*L_ + tid;
            float ip = g_ipre[(size_t)(b*S_+t)*NH_ + h];
            float2 bm = g_bm[(size_t)bh*S_ + t];
            uarr[tid] = expf(ip + Bn - bm.x - Mn);
        }
        if (tid == 0) lamp[0] = expf(Bn - Bc + Mc - Mn);
        __syncthreads();

        {
            int row = tid >> 2, col0 = (tid & 3) * 16;
            const float* kg = g_qk + ((size_t)(b*S_ + c*L_ + row))*QKS_ + 512 + h*DQK_ + col0;
            float u = uarr[row];
#pragma unroll
            for (int q4 = 0; q4 < 4; q4++) {
                float4 kk = *(const float4*)(kg + q4*4);
                Ks[row*68 + col0+q4*4+0] = kk.x * u;
                Ks[row*68 + col0+q4*4+1] = kk.y * u;
                Ks[row*68 + col0+q4*4+2] = kk.z * u;
                Ks[row*68 + col0+q4*4+3] = kk.w * u;
            }
            int vcol0 = (tid & 3) * 8;
            const float* vg = g_v + ((size_t)(b*S_ + c*L_ + row))*Vd_ + h*DHV_ + vq*32 + vcol0;
            float4 v0 = *(const float4*)vg;
            float4 v1 = *(const float4*)(vg + 4);
            Vs[row*36 + vcol0+0] = v0.x; Vs[row*36 + vcol0+1] = v0.y;
            Vs[row*36 + vcol0+2] = v0.z; Vs[row*36 + vcol0+3] = v0.w;
            Vs[row*36 + vcol0+4] = v1.x; Vs[row*36 + vcol0+5] = v1.y;
            Vs[row*36 + vcol0+6] = v1.z; Vs[row*36 + vcol0+7] = v1.w;
        }
        __syncthreads();

        float lam = lamp[0];
#pragma unroll
        for (int j = 0; j < 8; j++) acc[j] *= lam;

        for (int tau = 0; tau < L_; tau++) {
            float vv = Vs[tau*36 + tx];
            float4 k0 = *(const float4*)&Ks[tau*68 + ty*8];
            float4 k1 = *(const float4*)&Ks[tau*68 + ty*8 + 4];
            acc[0] = fmaf(k0.x, vv, acc[0]);
            acc[1] = fmaf(k0.y, vv, acc[1]);
            acc[2] = fmaf(k0.z, vv, acc[2]);
            acc[3] = fmaf(k0.w, vv, acc[3]);
            acc[4] = fmaf(k1.x, vv, acc[4]);
            acc[5] = fmaf(k1.y, vv, acc[5]);
            acc[6] = fmaf(k1.z, vv, acc[6]);
            acc[7] = fmaf(k1.w, vv, acc[7]);
        }

        if (vq == 0 && tid < DQK_) {
            float s = 0.f;
            for (int tau = 0; tau < L_; tau++) s += Ks[tau*68 + tid];
            narr[tid] = lam * narr[tid] + s;
        }

        Bc = Bn; Mc = Mn;
        __syncthreads();
    }
}

// ------- launch 2: qk-GEMM (128) + v-GEMM (128) + og-GEMM (128) + scan (16) -
__global__ __launch_bounds__(256, 2)
void proj_scan(const __nv_bfloat16* xhi, const __nv_bfloat16* xlo,
               const __nv_bfloat16* wqkhi, const __nv_bfloat16* wqklo,
               const __nv_bfloat16* wvhi, const __nv_bfloat16* wvlo,
               const __nv_bfloat16* woghi, const __nv_bfloat16* woglo,
               float* qk, float* v, float* opre)
{
    extern __shared__ __align__(16) unsigned char smem[];
    int x = blockIdx.x;
    if (x < 128) {
        gemm_body(xhi, xlo, wqkhi, wqklo, qk, D_, QKS_, smem, x & 7, x >> 3);
    } else if (x < 256) {
        x -= 128;
        gemm_body(xhi, xlo, wvhi, wvlo, v, D_, Vd_, smem, x & 7, x >> 3);
    } else if (x < 384) {
        x -= 256;
        gemm_body(xhi, xlo, woghi, woglo, opre, D_, Vd_, smem, x & 7, x >> 3);
    } else {
        scan_body((float*)smem, x - 384);
    }
}

// ---------------- launch 3: state_pass alone (64 CTAs, solo speed) ---------
__global__ __launch_bounds__(256)
void state_pass()
{
    extern __shared__ __align__(16) float smem_f[];
    state_body(smem_f, blockIdx.x & 3, blockIdx.x >> 2);
}

// ---------------- output GEMM ----------------------------------------------
__global__ __launch_bounds__(256, 2)
void gemm_out(const __nv_bfloat16* Ahi, const __nv_bfloat16* Alo,
              const __nv_bfloat16* Bhi, const __nv_bfloat16* Blo, float* C)
{
    extern __shared__ __align__(16) unsigned char smem[];
    gemm_body(Ahi, Alo, Bhi, Blo, C, Vd_, D_, smem, blockIdx.x, blockIdx.y);
}

// ---------------- chunk output: 256 threads + fused LN/gate ----------------
__global__ __launch_bounds__(256)
void chunk_out(const float* __restrict__ gamma)
{
    extern __shared__ float sm[];
    float* Qs  = sm;
    float* Kt  = Qs  + 64*68;
    float* Ps  = Kt  + 64*68;
    float* Vsh = Ps  + 64*68;
    float* Cs  = Vsh + 64*132;
    float* iar = Cs  + 16*132;
    float* bar = iar + 64;
    float* mar = bar + 64;
    float* alp = mar + 64;
    float* rsum= alp + 64;
    float* nq  = rsum+ 64;
    float* invd= nq  + 64;

    int c  = blockIdx.x;
    int bh = blockIdx.y;
    int b = bh >> 3, h = bh & 7;
    int tid = threadIdx.x;
    int ty = tid >> 4, tx = tid & 15;
    int s0 = c * L_;

    {
        int row = tid >> 2, col0 = (tid & 3) * 16;
        const float* qg = g_qk + ((size_t)(b*S_ + s0 + row))*QKS_ + h*DQK_ + col0;
        const float* kg = g_qk + ((size_t)(b*S_ + s0 + row))*QKS_ + 512 + h*DQK_ + col0;
#pragma unroll
        for (int q4 = 0; q4 < 4; q4++) {
            float4 qv = *(const float4*)(qg + q4*4);
            int d = col0 + q4*4;
            Qs[row*68 + d+0] = qv.x * 0.125f;
            Qs[row*68 + d+1] = qv.y * 0.125f;
            Qs[row*68 + d+2] = qv.z * 0.125f;
            Qs[row*68 + d+3] = qv.w * 0.125f;
            float4 kv = *(const float4*)(kg + q4*4);
            Kt[(d+0)*68 + row] = kv.x;
            Kt[(d+1)*68 + row] = kv.y;
            Kt[(d+2)*68 + row] = kv.z;
            Kt[(d+3)*68 + row] = kv.w;
        }
        int vcol0 = (tid & 3) * 32;
        const float* vg = g_v + ((size_t)(b*S_ + s0 + row))*Vd_ + h*DHV_ + vcol0;
#pragma unroll
        for (int q4 = 0; q4 < 8; q4++) {
            float4 vv = *(const float4*)(vg + q4*4);
            int vc = vcol0 + q4*4;
            Vsh[row*132 + vc+0] = vv.x;
            Vsh[row*132 + vc+1] = vv.y;
            Vsh[row*132 + vc+2] = vv.z;
            Vsh[row*132 + vc+3] = vv.w;
        }
    }
    if (tid < 64) {
        int t = s0 + tid;
        iar[tid] = g_ipre[(size_t)(b*S_+t)*NH_ + h];
        float2 bm = g_bm[(size_t)bh*S_ + t];
        bar[tid] = bm.x; mar[tid] = bm.y;
        nq[tid]  = (c > 0) ? g_nstate[(size_t)(bh*NC_ + c)*DQK_ + tid] : 0.f;
        rsum[tid] = 0.f;
    }
    __syncthreads();
    if (tid < 64) {
        float Bc = 0.f, Mc = 0.f;
        if (c > 0) { float2 bm = g_bm[(size_t)bh*S_ + s0 - 1]; Bc = bm.x; Mc = bm.y; }
        alp[tid] = expf(bar[tid] - Bc + Mc - mar[tid]);
    }

    float sAcc[4][4];
#pragma unroll
    for (int i = 0; i < 4; i++)
#pragma unroll
        for (int j = 0; j < 4; j++) sAcc[i][j] = 0.f;

    for (int d = 0; d < 64; d++) {
        float q0 = Qs[(ty*4+0)*68 + d];
        float q1 = Qs[(ty*4+1)*68 + d];
        float q2 = Qs[(ty*4+2)*68 + d];
        float q3 = Qs[(ty*4+3)*68 + d];
        float4 kt = *(const float4*)&Kt[d*68 + tx*4];
        sAcc[0][0] = fmaf(q0, kt.x, sAcc[0][0]); sAcc[0][1] = fmaf(q0, kt.y, sAcc[0][1]);
        sAcc[0][2] = fmaf(q0, kt.z, sAcc[0][2]); sAcc[0][3] = fmaf(q0, kt.w, sAcc[0][3]);
        sAcc[1][0] = fmaf(q1, kt.x, sAcc[1][0]); sAcc[1][1] = fmaf(q1, kt.y, sAcc[1][1]);
        sAcc[1][2] = fmaf(q1, kt.z, sAcc[1][2]); sAcc[1][3] = fmaf(q1, kt.w, sAcc[1][3]);
        sAcc[2][0] = fmaf(q2, kt.x, sAcc[2][0]); sAcc[2][1] = fmaf(q2, kt.y, sAcc[2][1]);
        sAcc[2][2] = fmaf(q2, kt.z, sAcc[2][2]); sAcc[2][3] = fmaf(q2, kt.w, sAcc[2][3]);
        sAcc[3][0] = fmaf(q3, kt.x, sAcc[3][0]); sAcc[3][1] = fmaf(q3, kt.y, sAcc[3][1]);
        sAcc[3][2] = fmaf(q3, kt.z, sAcc[3][2]); sAcc[3][3] = fmaf(q3, kt.w, sAcc[3][3]);
    }

    float rs[4] = {0.f, 0.f, 0.f, 0.f};
#pragma unroll
    for (int i = 0; i < 4; i++) {
        int t = ty*4 + i;
#pragma unroll
        for (int j = 0; j < 4; j++) {
            int ta = tx*4 + j;
            float w = (ta <= t) ? expf(iar[ta] + bar[t] - bar[ta] - mar[t]) : 0.f;
            float p = w * sAcc[i][j];
            Ps[t*68 + ta] = p;
            rs[i] += p;
        }
    }
#pragma unroll
    for (int off = 1; off < 16; off <<= 1) {
#pragma unroll
        for (int i = 0; i < 4; i++)
            rs[i] += __shfl_xor_sync(0xffffffffu, rs[i], off);
    }
    if (tx == 0) {
#pragma unroll
        for (int i = 0; i < 4; i++) rsum[ty*4 + i] = rs[i];
    }
    __syncthreads();

    float hAcc[4][8];
#pragma unroll
    for (int i = 0; i < 4; i++)
#pragma unroll
        for (int j = 0; j < 8; j++) hAcc[i][j] = 0.f;

    if (c > 0) {
        const float* stg = g_state + ((size_t)(bh*NC_ + c)) * (DQK_*DHV_);
        for (int r = 0; r < 4; r++) {
            {
                int dr = tid >> 4;
                int col0 = (tid & 15) * 8;
                const float* cg = stg + (r*16 + dr)*DHV_ + col0;
                float4 c0 = *(const float4*)cg;
                float4 c1 = *(const float4*)(cg + 4);
                Cs[dr*132 + col0+0] = c0.x; Cs[dr*132 + col0+1] = c0.y;
                Cs[dr*132 + col0+2] = c0.z; Cs[dr*132 + col0+3] = c0.w;
                Cs[dr*132 + col0+4] = c1.x; Cs[dr*132 + col0+5] = c1.y;
                Cs[dr*132 + col0+6] = c1.z; Cs[dr*132 + col0+7] = c1.w;
            }
            __syncthreads();
#pragma unroll
            for (int d = 0; d < 16; d++) {
                int dg = r*16 + d;
                float q0 = Qs[(ty*4+0)*68 + dg];
                float q1 = Qs[(ty*4+1)*68 + dg];
                float q2 = Qs[(ty*4+2)*68 + dg];
                float q3 = Qs[(ty*4+3)*68 + dg];
                float4 cv0 = *(const float4*)&Cs[d*132 + tx*8];
                float4 cv1 = *(const float4*)&Cs[d*132 + tx*8 + 4];
                hAcc[0][0]=fmaf(q0,cv0.x,hAcc[0][0]); hAcc[0][1]=fmaf(q0,cv0.y,hAcc[0][1]);
                hAcc[0][2]=fmaf(q0,cv0.z,hAcc[0][2]); hAcc[0][3]=fmaf(q0,cv0.w,hAcc[0][3]);
                hAcc[0][4]=fmaf(q0,cv1.x,hAcc[0][4]); hAcc[0][5]=fmaf(q0,cv1.y,hAcc[0][5]);
                hAcc[0][6]=fmaf(q0,cv1.z,hAcc[0][6]); hAcc[0][7]=fmaf(q0,cv1.w,hAcc[0][7]);
                hAcc[1][0]=fmaf(q1,cv0.x,hAcc[1][0]); hAcc[1][1]=fmaf(q1,cv0.y,hAcc[1][1]);
                hAcc[1][2]=fmaf(q1,cv0.z,hAcc[1][2]); hAcc[1][3]=fmaf(q1,cv0.w,hAcc[1][3]);
                hAcc[1][4]=fmaf(q1,cv1.x,hAcc[1][4]); hAcc[1][5]=fmaf(q1,cv1.y,hAcc[1][5]);
                hAcc[1][6]=fmaf(q1,cv1.z,hAcc[1][6]); hAcc[1][7]=fmaf(q1,cv1.w,hAcc[1][7]);
                hAcc[2][0]=fmaf(q2,cv0.x,hAcc[2][0]); hAcc[2][1]=fmaf(q2,cv0.y,hAcc[2][1]);
                hAcc[2][2]=fmaf(q2,cv0.z,hAcc[2][2]); hAcc[2][3]=fmaf(q2,cv0.w,hAcc[2][3]);
                hAcc[2][4]=fmaf(q2,cv1.x,hAcc[2][4]); hAcc[2][5]=fmaf(q2,cv1.y,hAcc[2][5]);
                hAcc[2][6]=fmaf(q2,cv1.z,hAcc[2][6]); hAcc[2][7]=fmaf(q2,cv1.w,hAcc[2][7]);
                hAcc[3][0]=fmaf(q3,cv0.x,hAcc[3][0]); hAcc[3][1]=fmaf(q3,cv0.y,hAcc[3][1]);
                hAcc[3][2]=fmaf(q3,cv0.z,hAcc[3][2]); hAcc[3][3]=fmaf(q3,cv0.w,hAcc[3][3]);
                hAcc[3][4]=fmaf(q3,cv1.x,hAcc[3][4]); hAcc[3][5]=fmaf(q3,cv1.y,hAcc[3][5]);
                hAcc[3][6]=fmaf(q3,cv1.z,hAcc[3][6]); hAcc[3][7]=fmaf(q3,cv1.w,hAcc[3][7]);
            }
            __syncthreads();
        }
#pragma unroll
        for (int i = 0; i < 4; i++) {
            float a = alp[ty*4 + i];
#pragma unroll
            for (int j = 0; j < 8; j++) hAcc[i][j] *= a;
        }
    }

    if (tid < 64) {
        float dq = 0.f;
        if (c > 0) {
            for (int d = 0; d < 64; d++) dq = fmaf(Qs[tid*68 + d], nq[d], dq);
            dq *= alp[tid];
        }
        float qn = dq + rsum[tid];
        float den = fmaxf(fabsf(qn), expf(-mar[tid])) + DENOM_EPS_;
        invd[tid] = 1.0f / den;
    }

    for (int ta = 0; ta < 64; ta += 4) {
        float4 pv0 = *(const float4*)&Ps[(ty*4+0)*68 + ta];
        float4 pv1 = *(const float4*)&Ps[(ty*4+1)*68 + ta];
        float4 pv2 = *(const float4*)&Ps[(ty*4+2)*68 + ta];
        float4 pv3 = *(const float4*)&Ps[(ty*4+3)*68 + ta];
#pragma unroll
        for (int jj = 0; jj < 4; jj++) {
            float4 v0 = *(const float4*)&Vsh[(ta+jj)*132 + tx*8];
            float4 v1 = *(const float4*)&Vsh[(ta+jj)*132 + tx*8 + 4];
            float p0 = (jj==0)?pv0.x:(jj==1)?pv0.y:(jj==2)?pv0.z:pv0.w;
            float p1 = (jj==0)?pv1.x:(jj==1)?pv1.y:(jj==2)?pv1.z:pv1.w;
            float p2 = (jj==0)?pv2.x:(jj==1)?pv2.y:(jj==2)?pv2.z:pv2.w;
            float p3 = (jj==0)?pv3.x:(jj==1)?pv3.y:(jj==2)?pv3.z:pv3.w;
            hAcc[0][0]=fmaf(p0,v0.x,hAcc[0][0]); hAcc[0][1]=fmaf(p0,v0.y,hAcc[0][1]);
            hAcc[0][2]=fmaf(p0,v0.z,hAcc[0][2]); hAcc[0][3]=fmaf(p0,v0.w,hAcc[0][3]);
            hAcc[0][4]=fmaf(p0,v1.x,hAcc[0][4]); hAcc[0][5]=fmaf(p0,v1.y,hAcc[0][5]);
            hAcc[0][6]=fmaf(p0,v1.z,hAcc[0][6]); hAcc[0][7]=fmaf(p0,v1.w,hAcc[0][7]);
            hAcc[1][0]=fmaf(p1,v0.x,hAcc[1][0]); hAcc[1][1]=fmaf(p1,v0.y,hAcc[1][1]);
            hAcc[1][2]=fmaf(p1,v0.z,hAcc[1][2]); hAcc[1][3]=fmaf(p1,v0.w,hAcc[1][3]);
            hAcc[1][4]=fmaf(p1,v1.x,hAcc[1][4]); hAcc[1][5]=fmaf(p1,v1.y,hAcc[1][5]);
            hAcc[1][6]=fmaf(p1,v1.z,hAcc[1][6]); hAcc[1][7]=fmaf(p1,v1.w,hAcc[1][7]);
            hAcc[2][0]=fmaf(p2,v0.x,hAcc[2][0]); hAcc[2][1]=fmaf(p2,v0.y,hAcc[2][1]);
            hAcc[2][2]=fmaf(p2,v0.z,hAcc[2][2]); hAcc[2][3]=fmaf(p2,v0.w,hAcc[2][3]);
            hAcc[2][4]=fmaf(p2,v1.x,hAcc[2][4]); hAcc[2][5]=fmaf(p2,v1.y,hAcc[2][5]);
            hAcc[2][6]=fmaf(p2,v1.z,hAcc[2][6]); hAcc[2][7]=fmaf(p2,v1.w,hAcc[2][7]);
            hAcc[3][0]=fmaf(p3,v0.x,hAcc[3][0]); hAcc[3][1]=fmaf(p3,v0.y,hAcc[3][1]);
            hAcc[3][2]=fmaf(p3,v0.z,hAcc[3][2]); hAcc[3][3]=fmaf(p3,v0.w,hAcc[3][3]);
            hAcc[3][4]=fmaf(p3,v1.x,hAcc[3][4]); hAcc[3][5]=fmaf(p3,v1.y,hAcc[3][5]);
            hAcc[3][6]=fmaf(p3,v1.z,hAcc[3][6]); hAcc[3][7]=fmaf(p3,v1.w,hAcc[3][7]);
        }
    }
    __syncthreads();

    const float* gm = gamma + (size_t)h*DHV_ + tx*8;
    float4 gm0 = *(const float4*)gm;
    float4 gm1 = *(const float4*)(gm + 4);
    float gmv[8] = {gm0.x, gm0.y, gm0.z, gm0.w, gm1.x, gm1.y, gm1.z, gm1.w};

#pragma unroll
    for (int i = 0; i < 4; i++) {
        int t = ty*4 + i;
        float id = invd[t];
        float hv[8];
#pragma unroll
        for (int j = 0; j < 8; j++) hv[j] = hAcc[i][j] * id;

        float sum = 0.f;
#pragma unroll
        for (int j = 0; j < 8; j++) sum += hv[j];
#pragma unroll
        for (int off = 1; off < 16; off <<= 1)
            sum += __shfl_xor_sync(0xffffffffu, sum, off);
        float mu = sum * (1.0f / 128.0f);

        float sq = 0.f;
#pragma unroll
        for (int j = 0; j < 8; j++) { float dd = hv[j] - mu; sq += dd * dd; }
#pragma unroll
        for (int off = 1; off < 16; off <<= 1)
            sq += __shfl_xor_sync(0xffffffffu, sq, off);
        float inv = rsqrtf(sq * (1.0f / 128.0f) + NORM_EPS_);

        const float* op = g_opre + ((size_t)(b*S_ + s0 + t))*Vd_ + h*DHV_ + tx*8;
        float4 op0 = *(const float4*)op;
        float4 op1 = *(const float4*)(op + 4);
        float sig[8];
        sig[0] = 1.f/(1.f+expf(-op0.x)); sig[1] = 1.f/(1.f+expf(-op0.y));
        sig[2] = 1.f/(1.f+expf(-op0.z)); sig[3] = 1.f/(1.f+expf(-op0.w));
        sig[4] = 1.f/(1.f+expf(-op1.x)); sig[5] = 1.f/(1.f+expf(-op1.y));
        sig[6] = 1.f/(1.f+expf(-op1.z)); sig[7] = 1.f/(1.f+expf(-op1.w));

        uint32_t hi4[4], lo4[4];
#pragma unroll
        for (int j2 = 0; j2 < 4; j2++) {
            float v0 = sig[j2*2]   * (hv[j2*2]   - mu) * inv * gmv[j2*2];
            float v1 = sig[j2*2+1] * (hv[j2*2+1] - mu) * inv * gmv[j2*2+1];
            __nv_bfloat16 h0 = __float2bfloat16(v0);
            __nv_bfloat16 h1 = __float2bfloat16(v1);
            __nv_bfloat16 l0 = __float2bfloat16(v0 - __bfloat162float(h0));
            __nv_bfloat16 l1 = __float2bfloat16(v1 - __bfloat162float(h1));
            hi4[j2] = (uint32_t)__bfloat16_as_ushort(h0) | ((uint32_t)__bfloat16_as_ushort(h1) << 16);
            lo4[j2] = (uint32_t)__bfloat16_as_ushort(l0) | ((uint32_t)__bfloat16_as_ushort(l1) << 16);
        }
        size_t idx = ((size_t)(b*S_ + s0 + t))*Vd_ + h*DHV_ + tx*8;
        *(uint4*)(g_hhi + idx) = make_uint4(hi4[0], hi4[1], hi4[2], hi4[3]);
        *(uint4*)(g_hlo + idx) = make_uint4(lo4[0], lo4[1], lo4[2], lo4[3]);
    }
}

// ------------------------------- launcher ---------------------------------
extern "C" void kernel_launch(void* const* d_in, const int* in_sizes, int n_in,
                              void* d_out, int out_size)
{
    const float* x    = (const float*)d_in[0];
    const float* Wq   = (const float*)d_in[1];
    const float* Wk   = (const float*)d_in[2];
    const float* Wv   = (const float*)d_in[3];
    const float* Wog  = (const float*)d_in[4];
    const float* Wi   = (const float*)d_in[5];
    const float* bi   = (const float*)d_in[6];
    const float* Wf   = (const float*)d_in[7];
    const float* bf   = (const float*)d_in[8];
    const float* gamma= (const float*)d_in[9];
    const float* Wout = (const float*)d_in[10];
    float* y = (float*)d_out;

    float *dqk, *dv, *dog;
    cudaGetSymbolAddress((void**)&dqk, g_qk);
    cudaGetSymbolAddress((void**)&dv,  g_v);
    cudaGetSymbolAddress((void**)&dog, g_opre);

    __nv_bfloat16 *xhi, *xlo, *wqkhi, *wqklo, *wvhi, *wvlo, *woghi, *woglo, *wouthi, *woutlo, *hhi, *hlo;
    cudaGetSymbolAddress((void**)&xhi,    g_xhi);
    cudaGetSymbolAddress((void**)&xlo,    g_xlo);
    cudaGetSymbolAddress((void**)&wqkhi,  g_wqkhi);
    cudaGetSymbolAddress((void**)&wqklo,  g_wqklo);
    cudaGetSymbolAddress((void**)&wvhi,   g_wvhi);
    cudaGetSymbolAddress((void**)&wvlo,   g_wvlo);
    cudaGetSymbolAddress((void**)&woghi,  g_woghi);
    cudaGetSymbolAddress((void**)&woglo,  g_woglo);
    cudaGetSymbolAddress((void**)&wouthi, g_wouthi);
    cudaGetSymbolAddress((void**)&woutlo, g_woutlo);
    cudaGetSymbolAddress((void**)&hhi,    g_hhi);
    cudaGetSymbolAddress((void**)&hlo,    g_hlo);

    const int M = B_ * S_;   // 2048
    const int CO_SMEM = (64*68*3 + 64*132 + 16*132 + 8*64) * 4;
    const int ST_SMEM = (64*68 + 64*36 + 64 + 64 + 4) * 4;   // ~27 KB
    const int GM_SMEM = 2 * GSTAGE;

    cudaFuncSetAttribute(chunk_out,  cudaFuncAttributeMaxDynamicSharedMemorySize, CO_SMEM);
    cudaFuncSetAttribute(proj_scan,  cudaFuncAttributeMaxDynamicSharedMemorySize, GM_SMEM);
    cudaFuncSetAttribute(state_pass, cudaFuncAttributeMaxDynamicSharedMemorySize, ST_SMEM);
    cudaFuncSetAttribute(gemm_out,   cudaFuncAttributeMaxDynamicSharedMemorySize, GM_SMEM);

    // ---- launch 1: conversions + gate projections ----
    int cvtBlocks;
    {
        CvtArgs a;
        int n = 0;
        a.src[0] = (const float4*)x;    a.hi[0] = (uint2*)xhi;              a.lo[0] = (uint2*)xlo;              n += (M*D_)/4;   a.end[0] = n;
        a.src[1] = (const float4*)Wq;   a.hi[1] = (uint2*)wqkhi;            a.lo[1] = (uint2*)wqklo;            n += (512*D_)/4; a.end[1] = n;
        a.src[2] = (const float4*)Wk;   a.hi[2] = (uint2*)(wqkhi + 512*D_); a.lo[2] = (uint2*)(wqklo + 512*D_); n += (512*D_)/4; a.end[2] = n;
        a.src[3] = (const float4*)Wv;   a.hi[3] = (uint2*)wvhi;             a.lo[3] = (uint2*)wvlo;             n += (Vd_*D_)/4; a.end[3] = n;
        a.src[4] = (const float4*)Wog;  a.hi[4] = (uint2*)woghi;            a.lo[4] = (uint2*)woglo;            n += (Vd_*D_)/4; a.end[4] = n;
        a.src[5] = (const float4*)Wout; a.hi[5] = (uint2*)wouthi;           a.lo[5] = (uint2*)woutlo;           n += (D_*Vd_)/4; a.end[5] = n;
        cvtBlocks = (n + 255) / 256;
        int gateBlocks = (M * 32 + 255) / 256;
        cvt_gates<<<cvtBlocks + gateBlocks, 256>>>(a, x, Wi, bi, Wf, bf, cvtBlocks);
    }

    // ---- launch 2: qk + v + og GEMMs + gate_scan (400 CTAs) ----
    proj_scan<<<400, 256, GM_SMEM>>>(xhi, xlo, wqkhi, wqklo, wvhi, wvlo,
                                     woghi, woglo, dqk, dv, dog);

    // ---- launch 3: state_pass alone (solo speed) ----
    state_pass<<<dim3(4 * B_ * NH_), 256, ST_SMEM>>>();

    // ---- launch 4: chunk output (LN + gate fused) ----
    chunk_out<<<dim3(NC_, B_*NH_), 256, CO_SMEM>>>(gamma);

    // ---- launch 5: output projection ----
    gemm_out<<<dim3(8, 16), 256, GM_SMEM>>>(hhi, hlo, wouthi, woutlo, y);
}

// round 14
// speedup vs baseline: 1.0486x; 1.0486x over previous
#include <cuda_runtime.h>
#include <cuda_bf16.h>
#include <math.h>
#include <stdint.h>

#define B_  2
#define S_  1024
#define D_  1024
#define NH_ 8
#define QKS_ 1024
#define Vd_ 1024
#define DQK_ 64
#define DHV_ 128
#define CAP_ 15.0f
#define NORM_EPS_ 1e-6f
#define DENOM_EPS_ 1e-6f
#define L_   64
#define NC_  (S_/L_)
#define NEGINF_ (-1e30f)

// ================= ptx helpers =================
__device__ __forceinline__ uint32_t smem_u32(const void* p) {
    uint32_t a;
    asm("{ .reg .u64 t; cvta.to.shared.u64 t, %1; cvt.u32.u64 %0, t; }" : "=r"(a) : "l"(p));
    return a;
}
#define CP_ASYNC16(dst, src) \
    asm volatile("cp.async.cg.shared.global [%0], [%1], 16;" :: "r"(dst), "l"(src))
#define CP_COMMIT() asm volatile("cp.async.commit_group;" ::: "memory")
#define CP_WAIT0()  asm volatile("cp.async.wait_group 0;" ::: "memory")
#define CP_WAIT1()  asm volatile("cp.async.wait_group 1;" ::: "memory")

#define LDMATRIX_X4(r0, r1, r2, r3, addr) \
    asm volatile("ldmatrix.sync.aligned.m8n8.x4.shared.b16 {%0,%1,%2,%3}, [%4];" \
        : "=r"(r0), "=r"(r1), "=r"(r2), "=r"(r3) : "r"(addr))

#define MMA16816(c, a, b0, b1) \
    asm volatile("mma.sync.aligned.m16n8k16.row.col.f32.bf16.bf16.f32 " \
        "{%0,%1,%2,%3}, {%4,%5,%6,%7}, {%8,%9}, {%0,%1,%2,%3};" \
        : "+f"((c)[0]), "+f"((c)[1]), "+f"((c)[2]), "+f"((c)[3]) \
        : "r"((a)[0]), "r"((a)[1]), "r"((a)[2]), "r"((a)[3]), "r"(b0), "r"(b1))

// ---------------- device scratch ----------------
__device__ float  g_qk  [B_*S_*QKS_];
__device__ float  g_v   [B_*S_*Vd_];
__device__ float  g_opre[B_*S_*Vd_];
__device__ float  g_ipre[B_*S_*NH_];
__device__ float  g_fpre[B_*S_*NH_];
__device__ float2 g_bm  [B_*NH_*S_];
__device__ float  g_state [B_*NH_*NC_*DQK_*DHV_];
__device__ float  g_nstate[B_*NH_*NC_*DQK_];

__device__ __align__(16) __nv_bfloat16 g_xhi[B_*S_*D_],  g_xlo[B_*S_*D_];
__device__ __align__(16) __nv_bfloat16 g_wqkhi[QKS_*D_], g_wqklo[QKS_*D_];
__device__ __align__(16) __nv_bfloat16 g_wvhi[Vd_*D_],   g_wvlo[Vd_*D_];
__device__ __align__(16) __nv_bfloat16 g_woghi[Vd_*D_],  g_woglo[Vd_*D_];
__device__ __align__(16) __nv_bfloat16 g_wouthi[D_*Vd_], g_woutlo[D_*Vd_];
__device__ __align__(16) __nv_bfloat16 g_hhi[B_*S_*Vd_], g_hlo[B_*S_*Vd_];

// ---------------- fused (cvt hi/lo split) + (gate projections) -------------
struct CvtArgs {
    const float4* src[6];
    uint2* hi[6];
    uint2* lo[6];
    int    end[6];
};

__device__ __forceinline__ float softcap15(float x) {
    return CAP_ * tanhf(x * (1.0f / CAP_));
}

__global__ __launch_bounds__(256)
void cvt_gates(CvtArgs a, const float* __restrict__ x,
               const float* __restrict__ Wi, const float* __restrict__ bi,
               const float* __restrict__ Wf, const float* __restrict__ bf,
               int cvtBlocks)
{
    if ((int)blockIdx.x < cvtBlocks) {
        int gi = blockIdx.x * 256 + threadIdx.x;
        if (gi >= a.end[5]) return;
        int seg = 0, base = 0;
#pragma unroll
        for (int s = 0; s < 5; s++)
            if (gi >= a.end[s]) { seg = s + 1; base = a.end[s]; }
        int i = gi - base;

        float4 v = a.src[seg][i];
        __nv_bfloat16 h0 = __float2bfloat16(v.x), h1 = __float2bfloat16(v.y);
        __nv_bfloat16 h2 = __float2bfloat16(v.z), h3 = __float2bfloat16(v.w);
        __nv_bfloat16 l0 = __float2bfloat16(v.x - __bfloat162float(h0));
        __nv_bfloat16 l1 = __float2bfloat16(v.y - __bfloat162float(h1));
        __nv_bfloat16 l2 = __float2bfloat16(v.z - __bfloat162float(h2));
        __nv_bfloat16 l3 = __float2bfloat16(v.w - __bfloat162float(h3));
        uint2 hv, lv;
        hv.x = (uint32_t)__bfloat16_as_ushort(h0) | ((uint32_t)__bfloat16_as_ushort(h1) << 16);
        hv.y = (uint32_t)__bfloat16_as_ushort(h2) | ((uint32_t)__bfloat16_as_ushort(h3) << 16);
        lv.x = (uint32_t)__bfloat16_as_ushort(l0) | ((uint32_t)__bfloat16_as_ushort(l1) << 16);
        lv.y = (uint32_t)__bfloat16_as_ushort(l2) | ((uint32_t)__bfloat16_as_ushort(l3) << 16);
        a.hi[seg][i] = hv;
        a.lo[seg][i] = lv;
    } else {
        int row  = ((blockIdx.x - cvtBlocks) * 256 + threadIdx.x) >> 5;
        int lane = threadIdx.x & 31;
        if (row >= B_ * S_) return;

        const float4* xr = (const float4*)(x + (size_t)row * D_);
        float4 xv[8];
#pragma unroll
        for (int k = 0; k < 8; k++) xv[k] = xr[lane + 32*k];

#pragma unroll
        for (int h = 0; h < NH_; h++) {
            const float4* wi = (const float4*)(Wi + (size_t)h * D_);
            const float4* wf = (const float4*)(Wf + (size_t)h * D_);
            float ai = 0.f, af = 0.f;
#pragma unroll
            for (int k = 0; k < 8; k++) {
                float4 iv = wi[lane + 32*k];
                float4 fv = wf[lane + 32*k];
                ai = fmaf(xv[k].x, iv.x, ai); ai = fmaf(xv[k].y, iv.y, ai);
                ai = fmaf(xv[k].z, iv.z, ai); ai = fmaf(xv[k].w, iv.w, ai);
                af = fmaf(xv[k].x, fv.x, af); af = fmaf(xv[k].y, fv.y, af);
                af = fmaf(xv[k].z, fv.z, af); af = fmaf(xv[k].w, fv.w, af);
            }
#pragma unroll
            for (int off = 16; off; off >>= 1) {
                ai += __shfl_xor_sync(0xffffffffu, ai, off);
                af += __shfl_xor_sync(0xffffffffu, af, off);
            }
            if (lane == 0) {
                g_ipre[row*NH_ + h] = softcap15(ai + bi[h]);
                g_fpre[row*NH_ + h] = softcap15(af + bf[h]);
            }
        }
    }
}

// ---------------- warp-MMA bf16x3-split GEMM body --------------------------
#define GSTAGE 40960
#define GMAT   10240

__device__ __forceinline__
void gemm_body(const __nv_bfloat16* __restrict__ Ahi, const __nv_bfloat16* __restrict__ Alo,
               const __nv_bfloat16* __restrict__ Bhi, const __nv_bfloat16* __restrict__ Blo,
               float* __restrict__ C, int K, int ldc,
               unsigned char* smem, int bx, int by)
{
    const uint32_t smem_base = smem_u32(smem);

    const int tid = threadIdx.x;
    const int wid = tid >> 5;
    const int lane = tid & 31;
    const int warp_m = wid & 3;
    const int warp_n = wid >> 2;
    const int blockRow = by * 128;
    const int blockCol = bx * 128;

    const __nv_bfloat16* bases[4] = {
        Ahi + (size_t)blockRow * K, Alo + (size_t)blockRow * K,
        Bhi + (size_t)blockCol * K, Blo + (size_t)blockCol * K };

    float acc[2][8][4];
#pragma unroll
    for (int i = 0; i < 2; i++)
#pragma unroll
        for (int j = 0; j < 8; j++)
#pragma unroll
            for (int q = 0; q < 4; q++) acc[i][j][q] = 0.f;

    const int nch = K >> 5;

#define LOAD_STAGE(buf, stage) do {                                            \
        const int kc0 = (stage) << 5;                                          \
        _Pragma("unroll")                                                      \
        for (int i = 0; i < 8; i++) {                                          \
            const int m  = i >> 1;                                             \
            const int cm = ((i & 1) << 8) + tid;                               \
            const int row = cm >> 2;                                           \
            const int cc  = cm & 3;                                            \
            const __nv_bfloat16* src = bases[m] + (size_t)row * K + kc0 + cc * 8; \
            uint32_t dst = smem_base + (buf) * GSTAGE + m * GMAT + row * 80 + cc * 16; \
            CP_ASYNC16(dst, src);                                              \
        }                                                                      \
        CP_COMMIT();                                                           \
    } while (0)

    LOAD_STAGE(0, 0);

    for (int c = 0; c < nch; c++) {
        const int buf = c & 1;
        if (c + 1 < nch) {
            LOAD_STAGE((c + 1) & 1, c + 1);
            CP_WAIT1();
        } else {
            CP_WAIT0();
        }
        __syncthreads();

        const uint32_t sa = smem_base + buf * GSTAGE + (warp_m * 32) * 80;
        const uint32_t sb = smem_base + buf * GSTAGE + 2 * GMAT + (warp_n * 64) * 80;
        const int a_row = lane & 15;
        const int a_kb  = (lane >> 4) << 4;
        const int b_row = (lane & 7) + ((lane >> 4) << 3);
        const int b_kb  = ((lane >> 3) & 1) << 4;

#pragma unroll
        for (int kk = 0; kk < 2; kk++) {
            uint32_t ah[2][4], al[2][4];
#pragma unroll
            for (int mt = 0; mt < 2; mt++) {
                uint32_t addr = sa + (mt * 16 + a_row) * 80 + kk * 32 + a_kb;
                LDMATRIX_X4(ah[mt][0], ah[mt][1], ah[mt][2], ah[mt][3], addr);
                addr += GMAT;
                LDMATRIX_X4(al[mt][0], al[mt][1], al[mt][2], al[mt][3], addr);
            }
#pragma unroll
            for (int gp = 0; gp < 2; gp++) {
                uint32_t bh[2][4], bl[2][4];
#pragma unroll
                for (int g2 = 0; g2 < 2; g2++) {
                    uint32_t addr = sb + ((gp * 2 + g2) * 16 + b_row) * 80 + kk * 32 + b_kb;
                    LDMATRIX_X4(bh[g2][0], bh[g2][1], bh[g2][2], bh[g2][3], addr);
                    addr += GMAT;
                    LDMATRIX_X4(bl[g2][0], bl[g2][1], bl[g2][2], bl[g2][3], addr);
                }
#pragma unroll
                for (int term = 0; term < 3; term++) {
#pragma unroll
                    for (int g2 = 0; g2 < 2; g2++)
#pragma unroll
                        for (int half = 0; half < 2; half++)
#pragma unroll
                            for (int mt = 0; mt < 2; mt++) {
                                const int nt = (gp * 2 + g2) * 2 + half;
                                const uint32_t* aa = (term == 2) ? al[mt] : ah[mt];
                                const uint32_t* bb = (term == 1) ? bl[g2] : bh[g2];
                                MMA16816(acc[mt][nt], aa, bb[half * 2], bb[half * 2 + 1]);
                            }
                }
            }
        }
        __syncthreads();
    }

    const int r0 = blockRow + warp_m * 32 + (lane >> 2);
    const int c0 = blockCol + warp_n * 64 + (lane & 3) * 2;
#pragma unroll
    for (int mt = 0; mt < 2; mt++) {
#pragma unroll
        for (int nt = 0; nt < 8; nt++) {
            float* p0 = C + (size_t)(r0 + mt * 16)     * ldc + c0 + nt * 8;
            float* p1 = C + (size_t)(r0 + mt * 16 + 8) * ldc + c0 + nt * 8;
            *(float2*)p0 = make_float2(acc[mt][nt][0], acc[mt][nt][1]);
            *(float2*)p1 = make_float2(acc[mt][nt][2], acc[mt][nt][3]);
        }
    }
#undef LOAD_STAGE
}

// ---------------- gate scan body: 256 threads, 4 timesteps/thread ----------
__device__ void scan_body(float* sm, int bh)
{
    float* wF = sm;
    float* wI = sm + 8;

    int b = bh >> 3, h = bh & 7;
    int tid = threadIdx.x, lane = tid & 31, warp = tid >> 5;
    int t0 = tid * 4;

    float Fe[4], Ie[4];
    float Fl = 0.f, Il = NEGINF_;
#pragma unroll
    for (int j = 0; j < 4; j++) {
        int t = t0 + j;
        float fp = g_fpre[(size_t)(b*S_+t)*NH_ + h];
        float ip = g_ipre[(size_t)(b*S_+t)*NH_ + h];
        float F = (fp >= 0.f) ? -log1pf(expf(-fp)) : (fp - log1pf(expf(fp)));
        Fe[j] = F; Ie[j] = ip;
        Il = fmaxf(Il + F, ip);
        Fl = Fl + F;
    }

    float Fi = Fl, Ii = Il;
#pragma unroll
    for (int off = 1; off < 32; off <<= 1) {
        float Fp = __shfl_up_sync(0xffffffffu, Fi, off);
        float Ip = __shfl_up_sync(0xffffffffu, Ii, off);
        if (lane >= off) {
            Ii = fmaxf(Ip + Fi, Ii);
            Fi = Fp + Fi;
        }
    }
    if (lane == 31) { wF[warp] = Fi; wI[warp] = Ii; }
    __syncthreads();

    if (warp == 0 && lane < 8) {
        float Fw = wF[lane], Iw = wI[lane];
#pragma unroll
        for (int off = 1; off < 8; off <<= 1) {
            float Fp = __shfl_up_sync(0x000000ffu, Fw, off);
            float Ip = __shfl_up_sync(0x000000ffu, Iw, off);
            if (lane >= off) {
                Iw = fmaxf(Ip + Fw, Iw);
                Fw = Fp + Fw;
            }
        }
        wF[lane] = Fw; wI[lane] = Iw;
    }
    __syncthreads();

    float Fprev = __shfl_up_sync(0xffffffffu, Fi, 1);
    float Iprev = __shfl_up_sync(0xffffffffu, Ii, 1);
    if (lane == 0) { Fprev = 0.f; Iprev = NEGINF_; }
    if (warp > 0) {
        float Fw = wF[warp - 1], Iw = wI[warp - 1];
        Iprev = fmaxf(Iw + Fprev, Iprev);
        Fprev = Fw + Fprev;
    }

    float Fc = Fprev, Ic = Iprev;
#pragma unroll
    for (int j = 0; j < 4; j++) {
        Ic = fmaxf(Ic + Fe[j], Ie[j]);
        Fc = Fc + Fe[j];
        g_bm[(size_t)bh*S_ + t0 + j] = make_float2(Fc, fmaxf(Fc, Ic));
    }
}

// ---------------- state pass body (uses dynamic smem) -----------------------
__device__ void state_body(float* sm, int vq, int bh)
{
    float* Ks   = sm;
    float* Vs   = Ks + 64*68;
    float* uarr = Vs + 64*36;
    float* narr = uarr + 64;
    float* lamp = narr + 64;

    int b = bh >> 3, h = bh & 7;
    int tid = threadIdx.x;
    int ty = tid >> 5;
    int tx = tid & 31;

    float acc[8];
#pragma unroll
    for (int j = 0; j < 8; j++) acc[j] = 0.f;
    if (tid < DQK_) narr[tid] = 0.f;

    float Bc = 0.f, Mc = 0.f;
    __syncthreads();

    for (int c = 0; c < NC_; c++) {
        float* st = g_state + ((size_t)(bh*NC_ + c)) * (DQK_*DHV_);
#pragma unroll
        for (int j = 0; j < 8; j++)
            st[(ty*8 + j)*DHV_ + vq*32 + tx] = acc[j];
        if (vq == 0 && tid < DQK_)
            g_nstate[(size_t)(bh*NC_ + c)*DQK_ + tid] = narr[tid];

        float2 bmn = g_bm[(size_t)bh*S_ + c*L_ + (L_-1)];
        float Bn = bmn.x, Mn = bmn.y;

        if (tid < L_) {
            int t = c*L_ + tid;
            float ip = g_ipre[(size_t)(b*S_+t)*NH_ + h];
            float2 bm = g_bm[(size_t)bh*S_ + t];
            uarr[tid] = expf(ip + Bn - bm.x - Mn);
        }
        if (tid == 0) lamp[0] = expf(Bn - Bc + Mc - Mn);
        __syncthreads();

        {
            int row = tid >> 2, col0 = (tid & 3) * 16;
            const float* kg = g_qk + ((size_t)(b*S_ + c*L_ + row))*QKS_ + 512 + h*DQK_ + col0;
            float u = uarr[row];
#pragma unroll
            for (int q4 = 0; q4 < 4; q4++) {
                float4 kk = *(const float4*)(kg + q4*4);
                Ks[row*68 + col0+q4*4+0] = kk.x * u;
                Ks[row*68 + col0+q4*4+1] = kk.y * u;
                Ks[row*68 + col0+q4*4+2] = kk.z * u;
                Ks[row*68 + col0+q4*4+3] = kk.w * u;
            }
            int vcol0 = (tid & 3) * 8;
            const float* vg = g_v + ((size_t)(b*S_ + c*L_ + row))*Vd_ + h*DHV_ + vq*32 + vcol0;
            float4 v0 = *(const float4*)vg;
            float4 v1 = *(const float4*)(vg + 4);
            Vs[row*36 + vcol0+0] = v0.x; Vs[row*36 + vcol0+1] = v0.y;
            Vs[row*36 + vcol0+2] = v0.z; Vs[row*36 + vcol0+3] = v0.w;
            Vs[row*36 + vcol0+4] = v1.x; Vs[row*36 + vcol0+5] = v1.y;
            Vs[row*36 + vcol0+6] = v1.z; Vs[row*36 + vcol0+7] = v1.w;
        }
        __syncthreads();

        float lam = lamp[0];
#pragma unroll
        for (int j = 0; j < 8; j++) acc[j] *= lam;

        for (int tau = 0; tau < L_; tau++) {
            float vv = Vs[tau*36 + tx];
            float4 k0 = *(const float4*)&Ks[tau*68 + ty*8];
            float4 k1 = *(const float4*)&Ks[tau*68 + ty*8 + 4];
            acc[0] = fmaf(k0.x, vv, acc[0]);
            acc[1] = fmaf(k0.y, vv, acc[1]);
            acc[2] = fmaf(k0.z, vv, acc[2]);
            acc[3] = fmaf(k0.w, vv, acc[3]);
            acc[4] = fmaf(k1.x, vv, acc[4]);
            acc[5] = fmaf(k1.y, vv, acc[5]);
            acc[6] = fmaf(k1.z, vv, acc[6]);
            acc[7] = fmaf(k1.w, vv, acc[7]);
        }

        if (vq == 0 && tid < DQK_) {
            float s = 0.f;
            for (int tau = 0; tau < L_; tau++) s += Ks[tau*68 + tid];
            narr[tid] = lam * narr[tid] + s;
        }

        Bc = Bn; Mc = Mn;
        __syncthreads();
    }
}

// ---------------- launch 2: qk-GEMM (128) + v-GEMM (128) + gate_scan (16) --
__global__ __launch_bounds__(256, 2)
void qkv_scan(const __nv_bfloat16* xhi, const __nv_bfloat16* xlo,
              const __nv_bfloat16* wqkhi, const __nv_bfloat16* wqklo,
              const __nv_bfloat16* wvhi, const __nv_bfloat16* wvlo,
              float* qk, float* v)
{
    extern __shared__ __align__(16) unsigned char smem[];
    int x = blockIdx.x;
    if (x < 128) {
        gemm_body(xhi, xlo, wqkhi, wqklo, qk, D_, QKS_, smem, x & 7, x >> 3);
    } else if (x < 256) {
        x -= 128;
        gemm_body(xhi, xlo, wvhi, wvlo, v, D_, Vd_, smem, x & 7, x >> 3);
    } else {
        scan_body((float*)smem, x - 256);
    }
}

// ---------------- launch 3: og-GEMM (128) + state_pass (64) ----------------
__global__ __launch_bounds__(256, 2)
void og_state_fused(const __nv_bfloat16* xhi, const __nv_bfloat16* xlo,
                    const __nv_bfloat16* woghi, const __nv_bfloat16* woglo,
                    float* opre)
{
    extern __shared__ __align__(16) unsigned char smem[];
    int x = blockIdx.x;
    if (x < 128) {
        gemm_body(xhi, xlo, woghi, woglo, opre, D_, Vd_, smem, x & 7, x >> 3);
    } else {
        int sid = x - 128;
        state_body((float*)smem, sid & 3, sid >> 2);
    }
}

// ---------------- output GEMM ----------------------------------------------
__global__ __launch_bounds__(256, 2)
void gemm_out(const __nv_bfloat16* Ahi, const __nv_bfloat16* Alo,
              const __nv_bfloat16* Bhi, const __nv_bfloat16* Blo, float* C)
{
    extern __shared__ __align__(16) unsigned char smem[];
    gemm_body(Ahi, Alo, Bhi, Blo, C, Vd_, D_, smem, blockIdx.x, blockIdx.y);
}

// ---------------- chunk output: Ps aliases Kt -> 79KB smem, 2 CTAs/SM ------
__global__ __launch_bounds__(256)
void chunk_out(const float* __restrict__ gamma)
{
    extern __shared__ float sm[];
    float* Qs  = sm;                 // [64][68]
    float* Kt  = Qs  + 64*68;        // [64][68]  (dead after S phase)
    float* Ps  = Kt;                 // ALIAS: Ps reuses Kt after sync
    float* Vsh = Kt  + 64*68;        // [64][132]
    float* Cs  = Vsh + 64*132;       // [16][132]
    float* iar = Cs  + 16*132;
    float* bar = iar + 64;
    float* mar = bar + 64;
    float* alp = mar + 64;
    float* rsum= alp + 64;
    float* nq  = rsum+ 64;
    float* invd= nq  + 64;

    int c  = blockIdx.x;
    int bh = blockIdx.y;
    int b = bh >> 3, h = bh & 7;
    int tid = threadIdx.x;
    int ty = tid >> 4, tx = tid & 15;
    int s0 = c * L_;

    {
        int row = tid >> 2, col0 = (tid & 3) * 16;
        const float* qg = g_qk + ((size_t)(b*S_ + s0 + row))*QKS_ + h*DQK_ + col0;
        const float* kg = g_qk + ((size_t)(b*S_ + s0 + row))*QKS_ + 512 + h*DQK_ + col0;
#pragma unroll
        for (int q4 = 0; q4 < 4; q4++) {
            float4 qv = *(const float4*)(qg + q4*4);
            int d = col0 + q4*4;
            Qs[row*68 + d+0] = qv.x * 0.125f;
            Qs[row*68 + d+1] = qv.y * 0.125f;
            Qs[row*68 + d+2] = qv.z * 0.125f;
            Qs[row*68 + d+3] = qv.w * 0.125f;
            float4 kv = *(const float4*)(kg + q4*4);
            Kt[(d+0)*68 + row] = kv.x;
            Kt[(d+1)*68 + row] = kv.y;
            Kt[(d+2)*68 + row] = kv.z;
            Kt[(d+3)*68 + row] = kv.w;
        }
        int vcol0 = (tid & 3) * 32;
        const float* vg = g_v + ((size_t)(b*S_ + s0 + row))*Vd_ + h*DHV_ + vcol0;
#pragma unroll
        for (int q4 = 0; q4 < 8; q4++) {
            float4 vv = *(const float4*)(vg + q4*4);
            int vc = vcol0 + q4*4;
            Vsh[row*132 + vc+0] = vv.x;
            Vsh[row*132 + vc+1] = vv.y;
            Vsh[row*132 + vc+2] = vv.z;
            Vsh[row*132 + vc+3] = vv.w;
        }
    }
    if (tid < 64) {
        int t = s0 + tid;
        iar[tid] = g_ipre[(size_t)(b*S_+t)*NH_ + h];
        float2 bm = g_bm[(size_t)bh*S_ + t];
        bar[tid] = bm.x; mar[tid] = bm.y;
        nq[tid]  = (c > 0) ? g_nstate[(size_t)(bh*NC_ + c)*DQK_ + tid] : 0.f;
        rsum[tid] = 0.f;
    }
    __syncthreads();
    if (tid < 64) {
        float Bc = 0.f, Mc = 0.f;
        if (c > 0) { float2 bm = g_bm[(size_t)bh*S_ + s0 - 1]; Bc = bm.x; Mc = bm.y; }
        alp[tid] = expf(bar[tid] - Bc + Mc - mar[tid]);
    }

    float sAcc[4][4];
#pragma unroll
    for (int i = 0; i < 4; i++)
#pragma unroll
        for (int j = 0; j < 4; j++) sAcc[i][j] = 0.f;

    for (int d = 0; d < 64; d++) {
        float q0 = Qs[(ty*4+0)*68 + d];
        float q1 = Qs[(ty*4+1)*68 + d];
        float q2 = Qs[(ty*4+2)*68 + d];
        float q3 = Qs[(ty*4+3)*68 + d];
        float4 kt = *(const float4*)&Kt[d*68 + tx*4];
        sAcc[0][0] = fmaf(q0, kt.x, sAcc[0][0]); sAcc[0][1] = fmaf(q0, kt.y, sAcc[0][1]);
        sAcc[0][2] = fmaf(q0, kt.z, sAcc[0][2]); sAcc[0][3] = fmaf(q0, kt.w, sAcc[0][3]);
        sAcc[1][0] = fmaf(q1, kt.x, sAcc[1][0]); sAcc[1][1] = fmaf(q1, kt.y, sAcc[1][1]);
        sAcc[1][2] = fmaf(q1, kt.z, sAcc[1][2]); sAcc[1][3] = fmaf(q1, kt.w, sAcc[1][3]);
        sAcc[2][0] = fmaf(q2, kt.x, sAcc[2][0]); sAcc[2][1] = fmaf(q2, kt.y, sAcc[2][1]);
        sAcc[2][2] = fmaf(q2, kt.z, sAcc[2][2]); sAcc[2][3] = fmaf(q2, kt.w, sAcc[2][3]);
        sAcc[3][0] = fmaf(q3, kt.x, sAcc[3][0]); sAcc[3][1] = fmaf(q3, kt.y, sAcc[3][1]);
        sAcc[3][2] = fmaf(q3, kt.z, sAcc[3][2]); sAcc[3][3] = fmaf(q3, kt.w, sAcc[3][3]);
    }
    __syncthreads();   // all Kt reads complete before Ps (same memory) is written

    float rs[4] = {0.f, 0.f, 0.f, 0.f};
#pragma unroll
    for (int i = 0; i < 4; i++) {
        int t = ty*4 + i;
#pragma unroll
        for (int j = 0; j < 4; j++) {
            int ta = tx*4 + j;
            float w = (ta <= t) ? expf(iar[ta] + bar[t] - bar[ta] - mar[t]) : 0.f;
            float p = w * sAcc[i][j];
            Ps[t*68 + ta] = p;
            rs[i] += p;
        }
    }
#pragma unroll
    for (int off = 1; off < 16; off <<= 1) {
#pragma unroll
        for (int i = 0; i < 4; i++)
            rs[i] += __shfl_xor_sync(0xffffffffu, rs[i], off);
    }
    if (tx == 0) {
#pragma unroll
        for (int i = 0; i < 4; i++) rsum[ty*4 + i] = rs[i];
    }
    __syncthreads();

    float hAcc[4][8];
#pragma unroll
    for (int i = 0; i < 4; i++)
#pragma unroll
        for (int j = 0; j < 8; j++) hAcc[i][j] = 0.f;

    if (c > 0) {
        const float* stg = g_state + ((size_t)(bh*NC_ + c)) * (DQK_*DHV_);
        for (int r = 0; r < 4; r++) {
            {
                int dr = tid >> 4;
                int col0 = (tid & 15) * 8;
                const float* cg = stg + (r*16 + dr)*DHV_ + col0;
                float4 c0 = *(const float4*)cg;
                float4 c1 = *(const float4*)(cg + 4);
                Cs[dr*132 + col0+0] = c0.x; Cs[dr*132 + col0+1] = c0.y;
                Cs[dr*132 + col0+2] = c0.z; Cs[dr*132 + col0+3] = c0.w;
                Cs[dr*132 + col0+4] = c1.x; Cs[dr*132 + col0+5] = c1.y;
                Cs[dr*132 + col0+6] = c1.z; Cs[dr*132 + col0+7] = c1.w;
            }
            __syncthreads();
#pragma unroll
            for (int d = 0; d < 16; d++) {
                int dg = r*16 + d;
                float q0 = Qs[(ty*4+0)*68 + dg];
                float q1 = Qs[(ty*4+1)*68 + dg];
                float q2 = Qs[(ty*4+2)*68 + dg];
                float q3 = Qs[(ty*4+3)*68 + dg];
                float4 cv0 = *(const float4*)&Cs[d*132 + tx*8];
                float4 cv1 = *(const float4*)&Cs[d*132 + tx*8 + 4];
                hAcc[0][0]=fmaf(q0,cv0.x,hAcc[0][0]); hAcc[0][1]=fmaf(q0,cv0.y,hAcc[0][1]);
                hAcc[0][2]=fmaf(q0,cv0.z,hAcc[0][2]); hAcc[0][3]=fmaf(q0,cv0.w,hAcc[0][3]);
                hAcc[0][4]=fmaf(q0,cv1.x,hAcc[0][4]); hAcc[0][5]=fmaf(q0,cv1.y,hAcc[0][5]);
                hAcc[0][6]=fmaf(q0,cv1.z,hAcc[0][6]); hAcc[0][7]=fmaf(q0,cv1.w,hAcc[0][7]);
                hAcc[1][0]=fmaf(q1,cv0.x,hAcc[1][0]); hAcc[1][1]=fmaf(q1,cv0.y,hAcc[1][1]);
                hAcc[1][2]=fmaf(q1,cv0.z,hAcc[1][2]); hAcc[1][3]=fmaf(q1,cv0.w,hAcc[1][3]);
                hAcc[1][4]=fmaf(q1,cv1.x,hAcc[1][4]); hAcc[1][5]=fmaf(q1,cv1.y,hAcc[1][5]);
                hAcc[1][6]=fmaf(q1,cv1.z,hAcc[1][6]); hAcc[1][7]=fmaf(q1,cv1.w,hAcc[1][7]);
                hAcc[2][0]=fmaf(q2,cv0.x,hAcc[2][0]); hAcc[2][1]=fmaf(q2,cv0.y,hAcc[2][1]);
                hAcc[2][2]=fmaf(q2,cv0.z,hAcc[2][2]); hAcc[2][3]=fmaf(q2,cv0.w,hAcc[2][3]);
                hAcc[2][4]=fmaf(q2,cv1.x,hAcc[2][4]); hAcc[2][5]=fmaf(q2,cv1.y,hAcc[2][5]);
                hAcc[2][6]=fmaf(q2,cv1.z,hAcc[2][6]); hAcc[2][7]=fmaf(q2,cv1.w,hAcc[2][7]);
                hAcc[3][0]=fmaf(q3,cv0.x,hAcc[3][0]); hAcc[3][1]=fmaf(q3,cv0.y,hAcc[3][1]);
                hAcc[3][2]=fmaf(q3,cv0.z,hAcc[3][2]); hAcc[3][3]=fmaf(q3,cv0.w,hAcc[3][3]);
                hAcc[3][4]=fmaf(q3,cv1.x,hAcc[3][4]); hAcc[3][5]=fmaf(q3,cv1.y,hAcc[3][5]);
                hAcc[3][6]=fmaf(q3,cv1.z,hAcc[3][6]); hAcc[3][7]=fmaf(q3,cv1.w,hAcc[3][7]);
            }
            __syncthreads();
        }
#pragma unroll
        for (int i = 0; i < 4; i++) {
            float a = alp[ty*4 + i];
#pragma unroll
            for (int j = 0; j < 8; j++) hAcc[i][j] *= a;
        }
    }

    if (tid < 64) {
        float dq = 0.f;
        if (c > 0) {
            for (int d = 0; d < 64; d++) dq = fmaf(Qs[tid*68 + d], nq[d], dq);
            dq *= alp[tid];
        }
        float qn = dq + rsum[tid];
        float den = fmaxf(fabsf(qn), expf(-mar[tid])) + DENOM_EPS_;
        invd[tid] = 1.0f / den;
    }

    for (int ta = 0; ta < 64; ta += 4) {
        float4 pv0 = *(const float4*)&Ps[(ty*4+0)*68 + ta];
        float4 pv1 = *(const float4*)&Ps[(ty*4+1)*68 + ta];
        float4 pv2 = *(const float4*)&Ps[(ty*4+2)*68 + ta];
        float4 pv3 = *(const float4*)&Ps[(ty*4+3)*68 + ta];
#pragma unroll
        for (int jj = 0; jj < 4; jj++) {
            float4 v0 = *(const float4*)&Vsh[(ta+jj)*132 + tx*8];
            float4 v1 = *(const float4*)&Vsh[(ta+jj)*132 + tx*8 + 4];
            float p0 = (jj==0)?pv0.x:(jj==1)?pv0.y:(jj==2)?pv0.z:pv0.w;
            float p1 = (jj==0)?pv1.x:(jj==1)?pv1.y:(jj==2)?pv1.z:pv1.w;
            float p2 = (jj==0)?pv2.x:(jj==1)?pv2.y:(jj==2)?pv2.z:pv2.w;
            float p3 = (jj==0)?pv3.x:(jj==1)?pv3.y:(jj==2)?pv3.z:pv3.w;
            hAcc[0][0]=fmaf(p0,v0.x,hAcc[0][0]); hAcc[0][1]=fmaf(p0,v0.y,hAcc[0][1]);
            hAcc[0][2]=fmaf(p0,v0.z,hAcc[0][2]); hAcc[0][3]=fmaf(p0,v0.w,hAcc[0][3]);
            hAcc[0][4]=fmaf(p0,v1.x,hAcc[0][4]); hAcc[0][5]=fmaf(p0,v1.y,hAcc[0][5]);
            hAcc[0][6]=fmaf(p0,v1.z,hAcc[0][6]); hAcc[0][7]=fmaf(p0,v1.w,hAcc[0][7]);
            hAcc[1][0]=fmaf(p1,v0.x,hAcc[1][0]); hAcc[1][1]=fmaf(p1,v0.y,hAcc[1][1]);
            hAcc[1][2]=fmaf(p1,v0.z,hAcc[1][2]); hAcc[1][3]=fmaf(p1,v0.w,hAcc[1][3]);
            hAcc[1][4]=fmaf(p1,v1.x,hAcc[1][4]); hAcc[1][5]=fmaf(p1,v1.y,hAcc[1][5]);
            hAcc[1][6]=fmaf(p1,v1.z,hAcc[1][6]); hAcc[1][7]=fmaf(p1,v1.w,hAcc[1][7]);
            hAcc[2][0]=fmaf(p2,v0.x,hAcc[2][0]); hAcc[2][1]=fmaf(p2,v0.y,hAcc[2][1]);
            hAcc[2][2]=fmaf(p2,v0.z,hAcc[2][2]); hAcc[2][3]=fmaf(p2,v0.w,hAcc[2][3]);
            hAcc[2][4]=fmaf(p2,v1.x,hAcc[2][4]); hAcc[2][5]=fmaf(p2,v1.y,hAcc[2][5]);
            hAcc[2][6]=fmaf(p2,v1.z,hAcc[2][6]); hAcc[2][7]=fmaf(p2,v1.w,hAcc[2][7]);
            hAcc[3][0]=fmaf(p3,v0.x,hAcc[3][0]); hAcc[3][1]=fmaf(p3,v0.y,hAcc[3][1]);
            hAcc[3][2]=fmaf(p3,v0.z,hAcc[3][2]); hAcc[3][3]=fmaf(p3,v0.w,hAcc[3][3]);
            hAcc[3][4]=fmaf(p3,v1.x,hAcc[3][4]); hAcc[3][5]=fmaf(p3,v1.y,hAcc[3][5]);
            hAcc[3][6]=fmaf(p3,v1.z,hAcc[3][6]); hAcc[3][7]=fmaf(p3,v1.w,hAcc[3][7]);
        }
    }
    __syncthreads();

    const float* gm = gamma + (size_t)h*DHV_ + tx*8;
    float4 gm0 = *(const float4*)gm;
    float4 gm1 = *(const float4*)(gm + 4);
    float gmv[8] = {gm0.x, gm0.y, gm0.z, gm0.w, gm1.x, gm1.y, gm1.z, gm1.w};

#pragma unroll
    for (int i = 0; i < 4; i++) {
        int t = ty*4 + i;
        float id = invd[t];
        float hv[8];
#pragma unroll
        for (int j = 0; j < 8; j++) hv[j] = hAcc[i][j] * id;

        float sum = 0.f;
#pragma unroll
        for (int j = 0; j < 8; j++) sum += hv[j];
#pragma unroll
        for (int off = 1; off < 16; off <<= 1)
            sum += __shfl_xor_sync(0xffffffffu, sum, off);
        float mu = sum * (1.0f / 128.0f);

        float sq = 0.f;
#pragma unroll
        for (int j = 0; j < 8; j++) { float dd = hv[j] - mu; sq += dd * dd; }
#pragma unroll
        for (int off = 1; off < 16; off <<= 1)
            sq += __shfl_xor_sync(0xffffffffu, sq, off);
        float inv = rsqrtf(sq * (1.0f / 128.0f) + NORM_EPS_);

        const float* op = g_opre + ((size_t)(b*S_ + s0 + t))*Vd_ + h*DHV_ + tx*8;
        float4 op0 = *(const float4*)op;
        float4 op1 = *(const float4*)(op + 4);
        float sig[8];
        sig[0] = 1.f/(1.f+expf(-op0.x)); sig[1] = 1.f/(1.f+expf(-op0.y));
        sig[2] = 1.f/(1.f+expf(-op0.z)); sig[3] = 1.f/(1.f+expf(-op0.w));
        sig[4] = 1.f/(1.f+expf(-op1.x)); sig[5] = 1.f/(1.f+expf(-op1.y));
        sig[6] = 1.f/(1.f+expf(-op1.z)); sig[7] = 1.f/(1.f+expf(-op1.w));

        uint32_t hi4[4], lo4[4];
#pragma unroll
        for (int j2 = 0; j2 < 4; j2++) {
            float v0 = sig[j2*2]   * (hv[j2*2]   - mu) * inv * gmv[j2*2];
            float v1 = sig[j2*2+1] * (hv[j2*2+1] - mu) * inv * gmv[j2*2+1];
            __nv_bfloat16 h0 = __float2bfloat16(v0);
            __nv_bfloat16 h1 = __float2bfloat16(v1);
            __nv_bfloat16 l0 = __float2bfloat16(v0 - __bfloat162float(h0));
            __nv_bfloat16 l1 = __float2bfloat16(v1 - __bfloat162float(h1));
            hi4[j2] = (uint32_t)__bfloat16_as_ushort(h0) | ((uint32_t)__bfloat16_as_ushort(h1) << 16);
            lo4[j2] = (uint32_t)__bfloat16_as_ushort(l0) | ((uint32_t)__bfloat16_as_ushort(l1) << 16);
        }
        size_t idx = ((size_t)(b*S_ + s0 + t))*Vd_ + h*DHV_ + tx*8;
        *(uint4*)(g_hhi + idx) = make_uint4(hi4[0], hi4[1], hi4[2], hi4[3]);
        *(uint4*)(g_hlo + idx) = make_uint4(lo4[0], lo4[1], lo4[2], lo4[3]);
    }
}

// ------------------------------- launcher ---------------------------------
extern "C" void kernel_launch(void* const* d_in, const int* in_sizes, int n_in,
                              void* d_out, int out_size)
{
    const float* x    = (const float*)d_in[0];
    const float* Wq   = (const float*)d_in[1];
    const float* Wk   = (const float*)d_in[2];
    const float* Wv   = (const float*)d_in[3];
    const float* Wog  = (const float*)d_in[4];
    const float* Wi   = (const float*)d_in[5];
    const float* bi   = (const float*)d_in[6];
    const float* Wf   = (const float*)d_in[7];
    const float* bf   = (const float*)d_in[8];
    const float* gamma= (const float*)d_in[9];
    const float* Wout = (const float*)d_in[10];
    float* y = (float*)d_out;

    float *dqk, *dv, *dog;
    cudaGetSymbolAddress((void**)&dqk, g_qk);
    cudaGetSymbolAddress((void**)&dv,  g_v);
    cudaGetSymbolAddress((void**)&dog, g_opre);

    __nv_bfloat16 *xhi, *xlo, *wqkhi, *wqklo, *wvhi, *wvlo, *woghi, *woglo, *wouthi, *woutlo, *hhi, *hlo;
    cudaGetSymbolAddress((void**)&xhi,    g_xhi);
    cudaGetSymbolAddress((void**)&xlo,    g_xlo);
    cudaGetSymbolAddress((void**)&wqkhi,  g_wqkhi);
    cudaGetSymbolAddress((void**)&wqklo,  g_wqklo);
    cudaGetSymbolAddress((void**)&wvhi,   g_wvhi);
    cudaGetSymbolAddress((void**)&wvlo,   g_wvlo);
    cudaGetSymbolAddress((void**)&woghi,  g_woghi);
    cudaGetSymbolAddress((void**)&woglo,  g_woglo);
    cudaGetSymbolAddress((void**)&wouthi, g_wouthi);
    cudaGetSymbolAddress((void**)&woutlo, g_woutlo);
    cudaGetSymbolAddress((void**)&hhi,    g_hhi);
    cudaGetSymbolAddress((void**)&hlo,    g_hlo);

    const int M = B_ * S_;   // 2048
    const int CO_SMEM = (64*68*2 + 64*132 + 16*132 + 8*64) * 4;   // ~79 KB (Ps aliases Kt)
    const int GM_SMEM = 2 * GSTAGE;

    cudaFuncSetAttribute(chunk_out,      cudaFuncAttributeMaxDynamicSharedMemorySize, CO_SMEM);
    cudaFuncSetAttribute(qkv_scan,       cudaFuncAttributeMaxDynamicSharedMemorySize, GM_SMEM);
    cudaFuncSetAttribute(og_state_fused, cudaFuncAttributeMaxDynamicSharedMemorySize, GM_SMEM);
    cudaFuncSetAttribute(gemm_out,       cudaFuncAttributeMaxDynamicSharedMemorySize, GM_SMEM);

    // ---- launch 1: conversions + gate projections ----
    int cvtBlocks;
    {
        CvtArgs a;
        int n = 0;
        a.src[0] = (const float4*)x;    a.hi[0] = (uint2*)xhi;              a.lo[0] = (uint2*)xlo;              n += (M*D_)/4;   a.end[0] = n;
        a.src[1] = (const float4*)Wq;   a.hi[1] = (uint2*)wqkhi;            a.lo[1] = (uint2*)wqklo;            n += (512*D_)/4; a.end[1] = n;
        a.src[2] = (const float4*)Wk;   a.hi[2] = (uint2*)(wqkhi + 512*D_); a.lo[2] = (uint2*)(wqklo + 512*D_); n += (512*D_)/4; a.end[2] = n;
        a.src[3] = (const float4*)Wv;   a.hi[3] = (uint2*)wvhi;             a.lo[3] = (uint2*)wvlo;             n += (Vd_*D_)/4; a.end[3] = n;
        a.src[4] = (const float4*)Wog;  a.hi[4] = (uint2*)woghi;            a.lo[4] = (uint2*)woglo;            n += (Vd_*D_)/4; a.end[4] = n;
        a.src[5] = (const float4*)Wout; a.hi[5] = (uint2*)wouthi;           a.lo[5] = (uint2*)woutlo;           n += (D_*Vd_)/4; a.end[5] = n;
        cvtBlocks = (n + 255) / 256;
        int gateBlocks = (M * 32 + 255) / 256;
        cvt_gates<<<cvtBlocks + gateBlocks, 256>>>(a, x, Wi, bi, Wf, bf, cvtBlocks);
    }

    // ---- launch 2: qk-GEMM + v-GEMM + gate_scan (272 CTAs, one wave) ----
    qkv_scan<<<272, 256, GM_SMEM>>>(xhi, xlo, wqkhi, wqklo, wvhi, wvlo, dqk, dv);

    // ---- launch 3: og-GEMM + state_pass ----
    og_state_fused<<<192, 256, GM_SMEM>>>(xhi, xlo, woghi, woglo, dog);

    // ---- launch 4: chunk output (LN + gate fused; 2 CTAs/SM) ----
    chunk_out<<<dim3(NC_, B_*NH_), 256, CO_SMEM>>>(gamma);

    // ---- launch 5: output projection ----
    gemm_out<<<dim3(8, 16), 256, GM_SMEM>>>(hhi, hlo, wouthi, woutlo, y);
}